// round 11
// baseline (speedup 1.0000x reference)
#include <cuda_runtime.h>
#include <math.h>

#define N_  8
#define S_  1024
#define F_  64
#define E_  512
#define H_  8
#define HD_ 64
#define L_  6
#define FF_ 2048
#define O_  64
#define NS_ (N_ * S_)

// ---------------- scratch (device globals; no allocations allowed) ----------
__device__ float g_h [NS_ * E_];
__device__ float g_hx[NS_ * E_];
__device__ float g_t [NS_ * E_];
__device__ float g_q [NS_ * E_];
__device__ float g_k [NS_ * E_];
__device__ float g_v [NS_ * E_];
__device__ float g_o [NS_ * E_];
__device__ float g_ff[NS_ * FF_];

// ---------------------------------------------------------------------------
// tf32 helpers: split fp32 into tf32-exact hi + tf32-rounded residual lo
// (both operands produced via cvt per PTX spec / CUTLASS 3xTF32 practice),
// and the m16n8k8 row.col tf32 mma (fragments per PTX ISA).
// ---------------------------------------------------------------------------
__device__ __forceinline__ void tf32_split(float x, unsigned& hi, unsigned& lo)
{
    unsigned h, l;
    asm("cvt.rna.tf32.f32 %0, %1;" : "=r"(h) : "f"(x));
    float resid = x - __uint_as_float(h);   // exact in fp32 (Sterbenz)
    asm("cvt.rna.tf32.f32 %0, %1;" : "=r"(l) : "f"(resid));
    hi = h;
    lo = l;
}

__device__ __forceinline__ void mma_m16n8k8(float* c, const unsigned* a,
                                            const unsigned* b)
{
    asm volatile(
        "mma.sync.aligned.m16n8k8.row.col.f32.tf32.tf32.f32 "
        "{%0,%1,%2,%3}, {%4,%5,%6,%7}, {%8,%9}, {%0,%1,%2,%3};\n"
        : "+f"(c[0]), "+f"(c[1]), "+f"(c[2]), "+f"(c[3])
        : "r"(a[0]), "r"(a[1]), "r"(a[2]), "r"(a[3]), "r"(b[0]), "r"(b[1]));
}

// ---------------------------------------------------------------------------
// Embedding: h[n][s][e] = relu(sum_f x[n][f][s] * W[f][e] + b[e]) + pos[s][e]
// grid (E/64, S/64, N), block 256, 64x64 tile, K=F=64
// ---------------------------------------------------------------------------
__global__ __launch_bounds__(256) void embed_kernel(
    const float* __restrict__ x, const float* __restrict__ W,
    const float* __restrict__ b, const float* __restrict__ pos,
    float* __restrict__ h)
{
    __shared__ float Xs[64][64];   // [f][s]
    __shared__ float Ws[64][64];   // [f][e]
    int t = threadIdx.x, tx = t & 15, ty = t >> 4;
    int e0 = blockIdx.x * 64, s0 = blockIdx.y * 64, n = blockIdx.z;

    #pragma unroll
    for (int it = 0; it < 4; it++) {
        int lin = t + it * 256;            // float4 index 0..1023
        int f = lin >> 4, c4 = (lin & 15) * 4;
        *(float4*)&Xs[f][c4] = *(const float4*)(x + (n * F_ + f) * S_ + s0 + c4);
        *(float4*)&Ws[f][c4] = *(const float4*)(W + f * E_ + e0 + c4);
    }
    __syncthreads();

    float acc[4][4] = {};
    #pragma unroll 8
    for (int f = 0; f < 64; f++) {
        float4 a4 = *(const float4*)&Xs[f][ty * 4];
        float4 b4 = *(const float4*)&Ws[f][tx * 4];
        float a[4] = {a4.x, a4.y, a4.z, a4.w};
        float bb[4] = {b4.x, b4.y, b4.z, b4.w};
        #pragma unroll
        for (int i = 0; i < 4; i++)
            #pragma unroll
            for (int j = 0; j < 4; j++) acc[i][j] += a[i] * bb[j];
    }

    #pragma unroll
    for (int i = 0; i < 4; i++) {
        int s = s0 + ty * 4 + i;
        int e = e0 + tx * 4;
        float4 r;
        r.x = fmaxf(acc[i][0] + b[e + 0], 0.f) + pos[s * E_ + e + 0];
        r.y = fmaxf(acc[i][1] + b[e + 1], 0.f) + pos[s * E_ + e + 1];
        r.z = fmaxf(acc[i][2] + b[e + 2], 0.f) + pos[s * E_ + e + 2];
        r.w = fmaxf(acc[i][3] + b[e + 3], 0.f) + pos[s * E_ + e + 3];
        *(float4*)&h[(n * S_ + s) * E_ + e] = r;
    }
}

// ---------------------------------------------------------------------------
// GEMM via tensor cores: tf32 mma.sync with hi/lo split compensation
// (hi*hi + hi*lo + lo*hi -> ~fp32 accuracy; error ~2^-22 per product).
// C[M x Nn] = A[M x K] @ B[K x Nn] + bias (opt relu)
// Block 256 (8 warps), tile 128x128, k-step 16 (2 x k8 mma sub-steps).
// Warp layout 2(M) x 4(N): warp tile 64x32 -> 4 m16-tiles x 4 n8-tiles.
// smem: As[m][16+4] (pad 20 -> frag banks 20g+tid4 all distinct),
//       Bs[k][128+8] (pad 136 -> bank step 8 -> 8tid4+g all distinct).
// Double buffered with register-staged LDG (load early, STS after compute).
// Requires M%128==0, Nn%128==0, K%16==0.
// ---------------------------------------------------------------------------
__global__ __launch_bounds__(256) void sgemm_tf32_kernel(
    const float* __restrict__ A, const float* __restrict__ B,
    const float* __restrict__ bias, float* __restrict__ C,
    int M, int Nn, int K, int relu)
{
    __shared__ __align__(16) float As[2][128][20];
    __shared__ __align__(16) float Bs[2][16][136];

    int t = threadIdx.x;
    int lane = t & 31, w = t >> 5;
    int g = lane >> 2, tid4 = lane & 3;
    int warpM = (w & 1) * 64;
    int warpN = (w >> 1) * 32;
    int m0 = blockIdx.y * 128, n0 = blockIdx.x * 128;

    // A loads: float4 ids t, t+256 -> rows t>>2 and 64+t>>2, k-quad t&3
    int arow = t >> 2, akq = t & 3;
    const float* Ap0 = A + (long)(m0 + arow) * K + akq * 4;
    const float* Ap1 = A + (long)(m0 + 64 + arow) * K + akq * 4;
    // B loads: float4 ids t, t+256 -> k rows t>>5 and 8+t>>5, n-quad (t&31)*4
    int bkr = t >> 5, bnq = (t & 31) * 4;
    const float* Bp0 = B + (long)bkr * Nn + n0 + bnq;
    const float* Bp1 = B + (long)(8 + bkr) * Nn + n0 + bnq;

    // prologue: tile 0 -> buf 0
    float4 a40 = *(const float4*)Ap0;
    float4 a41 = *(const float4*)Ap1;
    float4 b40 = *(const float4*)Bp0;
    float4 b41 = *(const float4*)Bp1;
    *(float4*)&As[0][arow][akq * 4]      = a40;
    *(float4*)&As[0][64 + arow][akq * 4] = a41;
    *(float4*)&Bs[0][bkr][bnq]           = b40;
    *(float4*)&Bs[0][8 + bkr][bnq]       = b41;
    __syncthreads();

    float c[4][4][4] = {};   // [mtile][ntile][frag]
    int buf = 0;
    for (int k0 = 0; k0 < K; k0 += 16) {
        bool has_next = (k0 + 16 < K);
        if (has_next) {                    // LDG early; STS after compute
            a40 = *(const float4*)(Ap0 + k0 + 16);
            a41 = *(const float4*)(Ap1 + k0 + 16);
            b40 = *(const float4*)(Bp0 + (long)(k0 + 16) * Nn);
            b41 = *(const float4*)(Bp1 + (long)(k0 + 16) * Nn);
        }
        #pragma unroll
        for (int ks = 0; ks < 2; ks++) {
            int kb = ks * 8;
            // B fragments for 4 n-tiles (hi/lo)
            unsigned bhi[4][2], blo[4][2];
            #pragma unroll
            for (int nt = 0; nt < 4; nt++) {
                int nb = warpN + nt * 8 + g;
                tf32_split(Bs[buf][kb + tid4][nb],     bhi[nt][0], blo[nt][0]);
                tf32_split(Bs[buf][kb + tid4 + 4][nb], bhi[nt][1], blo[nt][1]);
            }
            #pragma unroll
            for (int mt = 0; mt < 4; mt++) {
                int mb = warpM + mt * 16;
                unsigned ahi[4], alo[4];
                tf32_split(As[buf][mb + g][kb + tid4],          ahi[0], alo[0]);
                tf32_split(As[buf][mb + 8 + g][kb + tid4],      ahi[1], alo[1]);
                tf32_split(As[buf][mb + g][kb + tid4 + 4],      ahi[2], alo[2]);
                tf32_split(As[buf][mb + 8 + g][kb + tid4 + 4],  ahi[3], alo[3]);
                #pragma unroll
                for (int nt = 0; nt < 4; nt++) {
                    mma_m16n8k8(c[mt][nt], ahi, bhi[nt]);   // hi*hi
                    mma_m16n8k8(c[mt][nt], ahi, blo[nt]);   // hi*lo
                    mma_m16n8k8(c[mt][nt], alo, bhi[nt]);   // lo*hi
                }
            }
        }
        if (has_next) {
            int nb2 = buf ^ 1;
            *(float4*)&As[nb2][arow][akq * 4]      = a40;
            *(float4*)&As[nb2][64 + arow][akq * 4] = a41;
            *(float4*)&Bs[nb2][bkr][bnq]           = b40;
            *(float4*)&Bs[nb2][8 + bkr][bnq]       = b41;
            __syncthreads();
        }
        buf ^= 1;
    }

    // epilogue: c0,(g,2t) c1,(g,2t+1) c2,(g+8,2t) c3,(g+8,2t+1)
    #pragma unroll
    for (int mt = 0; mt < 4; mt++) {
        #pragma unroll
        for (int nt = 0; nt < 4; nt++) {
            int col = n0 + warpN + nt * 8 + tid4 * 2;
            float2 bv = *(const float2*)&bias[col];
            long r0 = m0 + warpM + mt * 16 + g;
            long r1 = r0 + 8;
            float v0 = c[mt][nt][0] + bv.x, v1 = c[mt][nt][1] + bv.y;
            float v2 = c[mt][nt][2] + bv.x, v3 = c[mt][nt][3] + bv.y;
            if (relu) {
                v0 = fmaxf(v0, 0.f); v1 = fmaxf(v1, 0.f);
                v2 = fmaxf(v2, 0.f); v3 = fmaxf(v3, 0.f);
            }
            *(float2*)&C[r0 * Nn + col] = make_float2(v0, v1);
            *(float2*)&C[r1 * Nn + col] = make_float2(v2, v3);
        }
    }
}

// ---------------------------------------------------------------------------
// QKV projection. h (NS x E) row-major; per head hh use cols [hh*64, hh*64+64).
// out[((n*H+hh)*S + s)*64 + e] = sum_d h[n,s,hh*64+d] * W[d][e] + b[e]
// grid (NS/64, H, 3), block 256
// ---------------------------------------------------------------------------
__global__ __launch_bounds__(256) void qkv_kernel(
    const float* __restrict__ hbuf,
    const float* __restrict__ Wq, const float* __restrict__ bq,
    const float* __restrict__ Wk, const float* __restrict__ bk,
    const float* __restrict__ Wv, const float* __restrict__ bv,
    float* __restrict__ qo, float* __restrict__ ko, float* __restrict__ vo)
{
    const float* W; const float* bb; float* out;
    if (blockIdx.z == 0)      { W = Wq; bb = bq; out = qo; }
    else if (blockIdx.z == 1) { W = Wk; bb = bk; out = ko; }
    else                      { W = Wv; bb = bv; out = vo; }
    int hh = blockIdx.y;
    int m0 = blockIdx.x * 64;

    __shared__ float As[64][64];   // [d][m]
    __shared__ float Bs[64][64];   // [d][e]
    int t = threadIdx.x, tx = t & 15, ty = t >> 4;

    int lm = t >> 2;
    #pragma unroll
    for (int kc = 0; kc < 4; kc++) {
        int lk = (t & 3) * 4 + kc * 16;
        float4 av = *(const float4*)(hbuf + (long)(m0 + lm) * E_ + hh * HD_ + lk);
        As[lk + 0][lm] = av.x; As[lk + 1][lm] = av.y;
        As[lk + 2][lm] = av.z; As[lk + 3][lm] = av.w;
    }
    #pragma unroll
    for (int it = 0; it < 4; it++) {
        int lin = t + it * 256;            // float4 index
        int kk = lin >> 4, ee = (lin & 15) * 4;
        *(float4*)&Bs[kk][ee] = *(const float4*)(W + kk * HD_ + ee);
    }
    __syncthreads();

    float acc[4][4] = {};
    #pragma unroll 8
    for (int d = 0; d < 64; d++) {
        float4 a4 = *(const float4*)&As[d][ty * 4];
        float4 b4 = *(const float4*)&Bs[d][tx * 4];
        float a[4] = {a4.x, a4.y, a4.z, a4.w};
        float b2[4] = {b4.x, b4.y, b4.z, b4.w};
        #pragma unroll
        for (int i = 0; i < 4; i++)
            #pragma unroll
            for (int j = 0; j < 4; j++) acc[i][j] += a[i] * b2[j];
    }

    #pragma unroll
    for (int i = 0; i < 4; i++) {
        int m = m0 + ty * 4 + i;
        int n = m >> 10, s = m & 1023;
        int e = tx * 4;
        float4 r;
        r.x = acc[i][0] + bb[e + 0];
        r.y = acc[i][1] + bb[e + 1];
        r.z = acc[i][2] + bb[e + 2];
        r.w = acc[i][3] + bb[e + 3];
        *(float4*)&out[((long)(n * H_ + hh) * S_ + s) * HD_ + e] = r;
    }
}

// ---------------------------------------------------------------------------
// Flash attention (fp32), 128 queries x 64 keys per tile, 8x4 per thread.
// Dynamic smem 96KB: Qts[64][128] | Kts[64][64] | Vs[64][64] | Ps[128][64].
// grid (S/128, N*H), block 256.
// ---------------------------------------------------------------------------
__global__ __launch_bounds__(256) void attn2_kernel(
    const float* __restrict__ q, const float* __restrict__ k,
    const float* __restrict__ v, float* __restrict__ obuf)
{
    extern __shared__ float sm[];
    float* Qts = sm;                 // [d][r]  64 x 128  (pre-scaled)
    float* Kts = Qts + 64 * 128;     // [d][j]  64 x 64
    float* Vs  = Kts + 64 * 64;      // [j][d]  64 x 64
    float* Ps  = Vs  + 64 * 64;      // [r][j] 128 x 64

    int t = threadIdx.x, tx = t & 15, ty = t >> 4;
    int nh = blockIdx.y;
    int n = nh >> 3, hh = nh & 7;
    int q0 = blockIdx.x * 128;
    const float* qb = q + ((long)nh * S_ + q0) * HD_;
    const float* kb = k + (long)nh * S_ * HD_;
    const float* vb = v + (long)nh * S_ * HD_;
    const float inv_scale = 0.044194173824159216f;  // 1/sqrt(512)

    // load Q transposed + scaled: 128 rows x 64 d
    {
        int lr = t >> 1;             // 0..127
        int bd = (t & 1) * 4;        // 0 or 4
        #pragma unroll
        for (int dc = 0; dc < 8; dc++) {
            int dd = bd + dc * 8;
            float4 f = *(const float4*)(qb + lr * HD_ + dd);
            Qts[(dd + 0) * 128 + lr] = f.x * inv_scale;
            Qts[(dd + 1) * 128 + lr] = f.y * inv_scale;
            Qts[(dd + 2) * 128 + lr] = f.z * inv_scale;
            Qts[(dd + 3) * 128 + lr] = f.w * inv_scale;
        }
    }

    float o[8][4] = {};
    float mrow[8], lrow[8];
    #pragma unroll
    for (int i = 0; i < 8; i++) { mrow[i] = -1e30f; lrow[i] = 0.f; }
    __syncthreads();

    int lr2 = t >> 2;                // 0..63 (K-transpose load row)
    for (int kt = 0; kt < 16; kt++) {
        const float* kbt = kb + (long)kt * 64 * HD_;
        const float* vbt = vb + (long)kt * 64 * HD_;
        // K transposed
        #pragma unroll
        for (int dc = 0; dc < 4; dc++) {
            int dd = (t & 3) * 4 + dc * 16;
            float4 f = *(const float4*)(kbt + lr2 * HD_ + dd);
            Kts[(dd + 0) * 64 + lr2] = f.x; Kts[(dd + 1) * 64 + lr2] = f.y;
            Kts[(dd + 2) * 64 + lr2] = f.z; Kts[(dd + 3) * 64 + lr2] = f.w;
        }
        // V straight copy (4096 floats)
        #pragma unroll
        for (int it = 0; it < 4; it++) {
            int lin = t + it * 256;
            ((float4*)Vs)[lin] = ((const float4*)vbt)[lin];
        }
        __syncthreads();

        // scores: rows ty*8..ty*8+7, cols tx*4..tx*4+3
        float s4[8][4] = {};
        #pragma unroll 8
        for (int d = 0; d < 64; d++) {
            float4 a40 = *(const float4*)&Qts[d * 128 + ty * 8];
            float4 a41 = *(const float4*)&Qts[d * 128 + ty * 8 + 4];
            float4 b4  = *(const float4*)&Kts[d * 64 + tx * 4];
            float a[8] = {a40.x, a40.y, a40.z, a40.w, a41.x, a41.y, a41.z, a41.w};
            float bb[4] = {b4.x, b4.y, b4.z, b4.w};
            #pragma unroll
            for (int i = 0; i < 8; i++)
                #pragma unroll
                for (int j = 0; j < 4; j++) s4[i][j] += a[i] * bb[j];
        }

        // online softmax (row reduction over 16 tx lanes)
        #pragma unroll
        for (int i = 0; i < 8; i++) {
            float mt = fmaxf(fmaxf(s4[i][0], s4[i][1]), fmaxf(s4[i][2], s4[i][3]));
            mt = fmaxf(mt, __shfl_xor_sync(0xffffffffu, mt, 1));
            mt = fmaxf(mt, __shfl_xor_sync(0xffffffffu, mt, 2));
            mt = fmaxf(mt, __shfl_xor_sync(0xffffffffu, mt, 4));
            mt = fmaxf(mt, __shfl_xor_sync(0xffffffffu, mt, 8));
            float mn = fmaxf(mrow[i], mt);
            float al = __expf(mrow[i] - mn);
            mrow[i] = mn;
            float ls = 0.f;
            #pragma unroll
            for (int j = 0; j < 4; j++) {
                float p = __expf(s4[i][j] - mn);
                s4[i][j] = p; ls += p;
            }
            ls += __shfl_xor_sync(0xffffffffu, ls, 1);
            ls += __shfl_xor_sync(0xffffffffu, ls, 2);
            ls += __shfl_xor_sync(0xffffffffu, ls, 4);
            ls += __shfl_xor_sync(0xffffffffu, ls, 8);
            lrow[i] = lrow[i] * al + ls;
            o[i][0] *= al; o[i][1] *= al; o[i][2] *= al; o[i][3] *= al;
        }

        // write P (Ps disjoint from Kts/Vs; prior PV finished at loop-end sync)
        #pragma unroll
        for (int i = 0; i < 8; i++)
            *(float4*)&Ps[(ty * 8 + i) * 64 + tx * 4] =
                make_float4(s4[i][0], s4[i][1], s4[i][2], s4[i][3]);
        __syncthreads();

        // O += P V
        #pragma unroll 4
        for (int jj = 0; jj < 64; jj++) {
            float4 b4 = *(const float4*)&Vs[jj * 64 + tx * 4];
            #pragma unroll
            for (int i = 0; i < 8; i++) {
                float p = Ps[(ty * 8 + i) * 64 + jj];
                o[i][0] += p * b4.x; o[i][1] += p * b4.y;
                o[i][2] += p * b4.z; o[i][3] += p * b4.w;
            }
        }
        __syncthreads();   // PV done before next tile overwrites Kts/Vs/Ps
    }

    #pragma unroll
    for (int i = 0; i < 8; i++) {
        float inv = 1.0f / lrow[i];
        int s = q0 + ty * 8 + i;
        float4 r = make_float4(o[i][0] * inv, o[i][1] * inv,
                               o[i][2] * inv, o[i][3] * inv);
        *(float4*)&obuf[((long)(n * S_ + s)) * E_ + hh * HD_ + tx * 4] = r;
    }
}

// ---------------------------------------------------------------------------
// out = LayerNorm(a + b) * g + be ; one block per row of 512, 128 threads
// ---------------------------------------------------------------------------
__global__ __launch_bounds__(128) void add_ln_kernel(
    const float* __restrict__ a, const float* __restrict__ b,
    const float* __restrict__ g, const float* __restrict__ be,
    float* __restrict__ out)
{
    __shared__ float sha[4], shb[4];
    int row = blockIdx.x, t = threadIdx.x;
    float4 x = ((const float4*)(a + (long)row * E_))[t];
    float4 y = ((const float4*)(b + (long)row * E_))[t];
    x.x += y.x; x.y += y.y; x.z += y.z; x.w += y.w;

    float s  = x.x + x.y + x.z + x.w;
    float s2 = x.x * x.x + x.y * x.y + x.z * x.z + x.w * x.w;
    #pragma unroll
    for (int m = 16; m; m >>= 1) {
        s  += __shfl_xor_sync(0xffffffffu, s,  m);
        s2 += __shfl_xor_sync(0xffffffffu, s2, m);
    }
    int w = t >> 5;
    if ((t & 31) == 0) { sha[w] = s; shb[w] = s2; }
    __syncthreads();
    s  = sha[0] + sha[1] + sha[2] + sha[3];
    s2 = shb[0] + shb[1] + shb[2] + shb[3];

    float mean = s * (1.0f / E_);
    float var  = s2 * (1.0f / E_) - mean * mean;
    float r    = rsqrtf(var + 1e-5f);

    int e = t * 4;
    float4 o;
    o.x = (x.x - mean) * r * g[e + 0] + be[e + 0];
    o.y = (x.y - mean) * r * g[e + 1] + be[e + 1];
    o.z = (x.z - mean) * r * g[e + 2] + be[e + 2];
    o.w = (x.w - mean) * r * g[e + 3] + be[e + 3];
    ((float4*)(out + (long)row * E_))[t] = o;
}

// ---------------------------------------------------------------------------
// Final pointwise conv: out[n][o][s] = sum_e h[n][s][e]*Wfin[e][o] + bfin[o]
// grid (NS/64), block 256; K=512, Nn=64, transposed store
// ---------------------------------------------------------------------------
__global__ __launch_bounds__(256) void final_kernel(
    const float* __restrict__ h, const float* __restrict__ Wfin,
    const float* __restrict__ bfin, float* __restrict__ out)
{
    __shared__ float As[16][64];
    __shared__ float Bs[16][64];
    int t = threadIdx.x, tx = t & 15, ty = t >> 4;
    int m0 = blockIdx.x * 64;

    int lm = t >> 2;
    int lk = (t & 3) * 4;
    int bk = t >> 4;
    int bn = (t & 15) * 4;
    const float* Aptr = h + (long)(m0 + lm) * E_ + lk;
    const float* Bptr = Wfin + (long)bk * O_ + bn;

    float acc[4][4] = {};
    for (int k0 = 0; k0 < E_; k0 += 16) {
        float4 av = *(const float4*)(Aptr + k0);
        As[lk + 0][lm] = av.x; As[lk + 1][lm] = av.y;
        As[lk + 2][lm] = av.z; As[lk + 3][lm] = av.w;
        *(float4*)&Bs[bk][bn] = *(const float4*)(Bptr + (long)k0 * O_);
        __syncthreads();
        #pragma unroll
        for (int kk = 0; kk < 16; kk++) {
            float4 a4 = *(const float4*)&As[kk][ty * 4];
            float4 b4 = *(const float4*)&Bs[kk][tx * 4];
            float a[4] = {a4.x, a4.y, a4.z, a4.w};
            float bb[4] = {b4.x, b4.y, b4.z, b4.w};
            #pragma unroll
            for (int i = 0; i < 4; i++)
                #pragma unroll
                for (int j = 0; j < 4; j++) acc[i][j] += a[i] * bb[j];
        }
        __syncthreads();
    }

    #pragma unroll
    for (int i = 0; i < 4; i++) {
        int m = m0 + ty * 4 + i;
        int n = m >> 10, s = m & 1023;
        #pragma unroll
        for (int j = 0; j < 4; j++) {
            int oo = tx * 4 + j;
            out[((long)(n * O_ + oo)) * S_ + s] = acc[i][j] + bfin[oo];
        }
    }
}

// ---------------------------------------------------------------------------
extern "C" void kernel_launch(void* const* d_in, const int* in_sizes, int n_in,
                              void* d_out, int out_size)
{
    (void)in_sizes; (void)n_in; (void)out_size;
    const float* x       = (const float*)d_in[0];
    const float* W_first = (const float*)d_in[1];
    const float* b_first = (const float*)d_in[2];
    const float* pos     = (const float*)d_in[3];
    const float* Wq      = (const float*)d_in[4];
    const float* bq      = (const float*)d_in[5];
    const float* Wk      = (const float*)d_in[6];
    const float* bk      = (const float*)d_in[7];
    const float* Wv      = (const float*)d_in[8];
    const float* bv      = (const float*)d_in[9];
    const float* Wo      = (const float*)d_in[10];
    const float* bo      = (const float*)d_in[11];
    const float* g1      = (const float*)d_in[12];
    const float* be1     = (const float*)d_in[13];
    const float* Wf1     = (const float*)d_in[14];
    const float* bf1     = (const float*)d_in[15];
    const float* Wf2     = (const float*)d_in[16];
    const float* bf2     = (const float*)d_in[17];
    const float* g2      = (const float*)d_in[18];
    const float* be2     = (const float*)d_in[19];
    const float* Wfin    = (const float*)d_in[20];
    const float* bfin    = (const float*)d_in[21];
    float* out = (float*)d_out;

    float *h, *hx, *tmp, *qb, *kb, *vb, *ob, *ff;
    cudaGetSymbolAddress((void**)&h,   g_h);
    cudaGetSymbolAddress((void**)&hx,  g_hx);
    cudaGetSymbolAddress((void**)&tmp, g_t);
    cudaGetSymbolAddress((void**)&qb,  g_q);
    cudaGetSymbolAddress((void**)&kb,  g_k);
    cudaGetSymbolAddress((void**)&vb,  g_v);
    cudaGetSymbolAddress((void**)&ob,  g_o);
    cudaGetSymbolAddress((void**)&ff,  g_ff);

    // Unconditional + idempotent (no static guards allowed; not a stream op,
    // so it is graph-capture-safe and deterministic on every call).
    const int ATTN_SMEM = 96 * 1024;
    cudaFuncSetAttribute(attn2_kernel,
                         cudaFuncAttributeMaxDynamicSharedMemorySize, ATTN_SMEM);

    embed_kernel<<<dim3(E_ / 64, S_ / 64, N_), 256>>>(x, W_first, b_first, pos, h);

    for (int l = 0; l < L_; l++) {
        qkv_kernel<<<dim3(NS_ / 64, H_, 3), 256>>>(
            h,
            Wq + (long)l * HD_ * HD_, bq + (long)l * HD_,
            Wk + (long)l * HD_ * HD_, bk + (long)l * HD_,
            Wv + (long)l * HD_ * HD_, bv + (long)l * HD_,
            qb, kb, vb);

        attn2_kernel<<<dim3(S_ / 128, N_ * H_), 256, ATTN_SMEM>>>(qb, kb, vb, ob);

        sgemm_tf32_kernel<<<dim3(E_ / 128, NS_ / 128), 256>>>(
            ob, Wo + (long)l * E_ * E_, bo + (long)l * E_, tmp,
            NS_, E_, E_, 0);

        add_ln_kernel<<<NS_, 128>>>(tmp, h, g1 + (long)l * E_, be1 + (long)l * E_, hx);

        sgemm_tf32_kernel<<<dim3(FF_ / 128, NS_ / 128), 256>>>(
            hx, Wf1 + (long)l * E_ * FF_, bf1 + (long)l * FF_, ff,
            NS_, FF_, E_, 1);

        sgemm_tf32_kernel<<<dim3(E_ / 128, NS_ / 128), 256>>>(
            ff, Wf2 + (long)l * FF_ * E_, bf2 + (long)l * E_, tmp,
            NS_, E_, FF_, 0);

        add_ln_kernel<<<NS_, 128>>>(tmp, hx, g2 + (long)l * E_, be2 + (long)l * E_, h);
    }

    final_kernel<<<NS_ / 64, 256>>>(h, Wfin, bfin, out);
}

// round 14
// speedup vs baseline: 1.0719x; 1.0719x over previous
#include <cuda_runtime.h>
#include <math.h>

#define N_  8
#define S_  1024
#define F_  64
#define E_  512
#define H_  8
#define HD_ 64
#define L_  6
#define FF_ 2048
#define O_  64
#define NS_ (N_ * S_)

// ---------------- scratch (device globals; no allocations allowed) ----------
__device__ float g_h [NS_ * E_];
__device__ float g_hx[NS_ * E_];
__device__ float g_t [NS_ * E_];
__device__ float g_q [NS_ * E_];
__device__ float g_k [NS_ * E_];
__device__ float g_v [NS_ * E_];
__device__ float g_o [NS_ * E_];
__device__ float g_ff[NS_ * FF_];

// ---------------------------------------------------------------------------
// tf32 helpers (validated in R11 pass): hi = cvt(x), lo = cvt(x - hi);
// m16n8k8 row.col tf32 mma, fragments per PTX ISA.
// ---------------------------------------------------------------------------
__device__ __forceinline__ void tf32_split(float x, unsigned& hi, unsigned& lo)
{
    unsigned h, l;
    asm("cvt.rna.tf32.f32 %0, %1;" : "=r"(h) : "f"(x));
    float resid = x - __uint_as_float(h);   // exact in fp32 (Sterbenz)
    asm("cvt.rna.tf32.f32 %0, %1;" : "=r"(l) : "f"(resid));
    hi = h;
    lo = l;
}

__device__ __forceinline__ void mma_m16n8k8(float* c, const unsigned* a,
                                            const unsigned* b)
{
    asm volatile(
        "mma.sync.aligned.m16n8k8.row.col.f32.tf32.tf32.f32 "
        "{%0,%1,%2,%3}, {%4,%5,%6,%7}, {%8,%9}, {%0,%1,%2,%3};\n"
        : "+f"(c[0]), "+f"(c[1]), "+f"(c[2]), "+f"(c[3])
        : "r"(a[0]), "r"(a[1]), "r"(a[2]), "r"(a[3]), "r"(b[0]), "r"(b[1]));
}

// ---------------------------------------------------------------------------
// Embedding: h[n][s][e] = relu(sum_f x[n][f][s] * W[f][e] + b[e]) + pos[s][e]
// grid (E/64, S/64, N), block 256, 64x64 tile, K=F=64
// ---------------------------------------------------------------------------
__global__ __launch_bounds__(256) void embed_kernel(
    const float* __restrict__ x, const float* __restrict__ W,
    const float* __restrict__ b, const float* __restrict__ pos,
    float* __restrict__ h)
{
    __shared__ float Xs[64][64];   // [f][s]
    __shared__ float Ws[64][64];   // [f][e]
    int t = threadIdx.x, tx = t & 15, ty = t >> 4;
    int e0 = blockIdx.x * 64, s0 = blockIdx.y * 64, n = blockIdx.z;

    #pragma unroll
    for (int it = 0; it < 4; it++) {
        int lin = t + it * 256;            // float4 index 0..1023
        int f = lin >> 4, c4 = (lin & 15) * 4;
        *(float4*)&Xs[f][c4] = *(const float4*)(x + (n * F_ + f) * S_ + s0 + c4);
        *(float4*)&Ws[f][c4] = *(const float4*)(W + f * E_ + e0 + c4);
    }
    __syncthreads();

    float acc[4][4] = {};
    #pragma unroll 8
    for (int f = 0; f < 64; f++) {
        float4 a4 = *(const float4*)&Xs[f][ty * 4];
        float4 b4 = *(const float4*)&Ws[f][tx * 4];
        float a[4] = {a4.x, a4.y, a4.z, a4.w};
        float bb[4] = {b4.x, b4.y, b4.z, b4.w};
        #pragma unroll
        for (int i = 0; i < 4; i++)
            #pragma unroll
            for (int j = 0; j < 4; j++) acc[i][j] += a[i] * bb[j];
    }

    #pragma unroll
    for (int i = 0; i < 4; i++) {
        int s = s0 + ty * 4 + i;
        int e = e0 + tx * 4;
        float4 r;
        r.x = fmaxf(acc[i][0] + b[e + 0], 0.f) + pos[s * E_ + e + 0];
        r.y = fmaxf(acc[i][1] + b[e + 1], 0.f) + pos[s * E_ + e + 1];
        r.z = fmaxf(acc[i][2] + b[e + 2], 0.f) + pos[s * E_ + e + 2];
        r.w = fmaxf(acc[i][3] + b[e + 3], 0.f) + pos[s * E_ + e + 3];
        *(float4*)&h[(n * S_ + s) * E_ + e] = r;
    }
}

// ---------------------------------------------------------------------------
// GEMM via tensor cores (validated R11): tf32 mma with hi/lo compensation.
// C[M x Nn] = A[M x K] @ B[K x Nn] + bias (opt relu)
// ---------------------------------------------------------------------------
__global__ __launch_bounds__(256) void sgemm_tf32_kernel(
    const float* __restrict__ A, const float* __restrict__ B,
    const float* __restrict__ bias, float* __restrict__ C,
    int M, int Nn, int K, int relu)
{
    __shared__ __align__(16) float As[2][128][20];
    __shared__ __align__(16) float Bs[2][16][136];

    int t = threadIdx.x;
    int lane = t & 31, w = t >> 5;
    int g = lane >> 2, tid4 = lane & 3;
    int warpM = (w & 1) * 64;
    int warpN = (w >> 1) * 32;
    int m0 = blockIdx.y * 128, n0 = blockIdx.x * 128;

    int arow = t >> 2, akq = t & 3;
    const float* Ap0 = A + (long)(m0 + arow) * K + akq * 4;
    const float* Ap1 = A + (long)(m0 + 64 + arow) * K + akq * 4;
    int bkr = t >> 5, bnq = (t & 31) * 4;
    const float* Bp0 = B + (long)bkr * Nn + n0 + bnq;
    const float* Bp1 = B + (long)(8 + bkr) * Nn + n0 + bnq;

    float4 a40 = *(const float4*)Ap0;
    float4 a41 = *(const float4*)Ap1;
    float4 b40 = *(const float4*)Bp0;
    float4 b41 = *(const float4*)Bp1;
    *(float4*)&As[0][arow][akq * 4]      = a40;
    *(float4*)&As[0][64 + arow][akq * 4] = a41;
    *(float4*)&Bs[0][bkr][bnq]           = b40;
    *(float4*)&Bs[0][8 + bkr][bnq]       = b41;
    __syncthreads();

    float c[4][4][4] = {};   // [mtile][ntile][frag]
    int buf = 0;
    for (int k0 = 0; k0 < K; k0 += 16) {
        bool has_next = (k0 + 16 < K);
        if (has_next) {
            a40 = *(const float4*)(Ap0 + k0 + 16);
            a41 = *(const float4*)(Ap1 + k0 + 16);
            b40 = *(const float4*)(Bp0 + (long)(k0 + 16) * Nn);
            b41 = *(const float4*)(Bp1 + (long)(k0 + 16) * Nn);
        }
        #pragma unroll
        for (int ks = 0; ks < 2; ks++) {
            int kb = ks * 8;
            unsigned bhi[4][2], blo[4][2];
            #pragma unroll
            for (int nt = 0; nt < 4; nt++) {
                int nb = warpN + nt * 8 + g;
                tf32_split(Bs[buf][kb + tid4][nb],     bhi[nt][0], blo[nt][0]);
                tf32_split(Bs[buf][kb + tid4 + 4][nb], bhi[nt][1], blo[nt][1]);
            }
            #pragma unroll
            for (int mt = 0; mt < 4; mt++) {
                int mb = warpM + mt * 16;
                unsigned ahi[4], alo[4];
                tf32_split(As[buf][mb + g][kb + tid4],          ahi[0], alo[0]);
                tf32_split(As[buf][mb + 8 + g][kb + tid4],      ahi[1], alo[1]);
                tf32_split(As[buf][mb + g][kb + tid4 + 4],      ahi[2], alo[2]);
                tf32_split(As[buf][mb + 8 + g][kb + tid4 + 4],  ahi[3], alo[3]);
                #pragma unroll
                for (int nt = 0; nt < 4; nt++) {
                    mma_m16n8k8(c[mt][nt], ahi, bhi[nt]);   // hi*hi
                    mma_m16n8k8(c[mt][nt], ahi, blo[nt]);   // hi*lo
                    mma_m16n8k8(c[mt][nt], alo, bhi[nt]);   // lo*hi
                }
            }
        }
        if (has_next) {
            int nb2 = buf ^ 1;
            *(float4*)&As[nb2][arow][akq * 4]      = a40;
            *(float4*)&As[nb2][64 + arow][akq * 4] = a41;
            *(float4*)&Bs[nb2][bkr][bnq]           = b40;
            *(float4*)&Bs[nb2][8 + bkr][bnq]       = b41;
            __syncthreads();
        }
        buf ^= 1;
    }

    #pragma unroll
    for (int mt = 0; mt < 4; mt++) {
        #pragma unroll
        for (int nt = 0; nt < 4; nt++) {
            int col = n0 + warpN + nt * 8 + tid4 * 2;
            float2 bv = *(const float2*)&bias[col];
            long r0 = m0 + warpM + mt * 16 + g;
            long r1 = r0 + 8;
            float v0 = c[mt][nt][0] + bv.x, v1 = c[mt][nt][1] + bv.y;
            float v2 = c[mt][nt][2] + bv.x, v3 = c[mt][nt][3] + bv.y;
            if (relu) {
                v0 = fmaxf(v0, 0.f); v1 = fmaxf(v1, 0.f);
                v2 = fmaxf(v2, 0.f); v3 = fmaxf(v3, 0.f);
            }
            *(float2*)&C[r0 * Nn + col] = make_float2(v0, v1);
            *(float2*)&C[r1 * Nn + col] = make_float2(v2, v3);
        }
    }
}

// ---------------------------------------------------------------------------
// QKV projection. h (NS x E) row-major; per head hh use cols [hh*64, hh*64+64).
// grid (NS/64, H, 3), block 256
// ---------------------------------------------------------------------------
__global__ __launch_bounds__(256) void qkv_kernel(
    const float* __restrict__ hbuf,
    const float* __restrict__ Wq, const float* __restrict__ bq,
    const float* __restrict__ Wk, const float* __restrict__ bk,
    const float* __restrict__ Wv, const float* __restrict__ bv,
    float* __restrict__ qo, float* __restrict__ ko, float* __restrict__ vo)
{
    const float* W; const float* bb; float* out;
    if (blockIdx.z == 0)      { W = Wq; bb = bq; out = qo; }
    else if (blockIdx.z == 1) { W = Wk; bb = bk; out = ko; }
    else                      { W = Wv; bb = bv; out = vo; }
    int hh = blockIdx.y;
    int m0 = blockIdx.x * 64;

    __shared__ float As[64][64];   // [d][m]
    __shared__ float Bs[64][64];   // [d][e]
    int t = threadIdx.x, tx = t & 15, ty = t >> 4;

    int lm = t >> 2;
    #pragma unroll
    for (int kc = 0; kc < 4; kc++) {
        int lk = (t & 3) * 4 + kc * 16;
        float4 av = *(const float4*)(hbuf + (long)(m0 + lm) * E_ + hh * HD_ + lk);
        As[lk + 0][lm] = av.x; As[lk + 1][lm] = av.y;
        As[lk + 2][lm] = av.z; As[lk + 3][lm] = av.w;
    }
    #pragma unroll
    for (int it = 0; it < 4; it++) {
        int lin = t + it * 256;            // float4 index
        int kk = lin >> 4, ee = (lin & 15) * 4;
        *(float4*)&Bs[kk][ee] = *(const float4*)(W + kk * HD_ + ee);
    }
    __syncthreads();

    float acc[4][4] = {};
    #pragma unroll 8
    for (int d = 0; d < 64; d++) {
        float4 a4 = *(const float4*)&As[d][ty * 4];
        float4 b4 = *(const float4*)&Bs[d][tx * 4];
        float a[4] = {a4.x, a4.y, a4.z, a4.w};
        float b2[4] = {b4.x, b4.y, b4.z, b4.w};
        #pragma unroll
        for (int i = 0; i < 4; i++)
            #pragma unroll
            for (int j = 0; j < 4; j++) acc[i][j] += a[i] * b2[j];
    }

    #pragma unroll
    for (int i = 0; i < 4; i++) {
        int m = m0 + ty * 4 + i;
        int n = m >> 10, s = m & 1023;
        int e = tx * 4;
        float4 r;
        r.x = acc[i][0] + bb[e + 0];
        r.y = acc[i][1] + bb[e + 1];
        r.z = acc[i][2] + bb[e + 2];
        r.w = acc[i][3] + bb[e + 3];
        *(float4*)&out[((long)(n * H_ + hh) * S_ + s) * HD_ + e] = r;
    }
}

// ---------------------------------------------------------------------------
// Flash attention on tensor cores (tf32 hi/lo compensated, same maps as GEMM).
// Block 256 = 8 warps; warp w owns q rows [w*16, w*16+16) of a 128-q tile.
// Per 64-key tile: S = Q K^T via mma (8 n-tiles x 8 k-chunks x 3 mma),
// fragment-level online softmax (lane owns rows g and g+8; reduce over tid4
// quad via shfl 1,2), P -> smem (warp-private rows), O += P V via mma.
// smem (floats, rows padded to 68 for conflict-free frag access):
//   Qs[128][68] | Ks[64][68] | Vs[64][68] | Ps[128][68]  = 104448 B dynamic.
// grid (S/128, N*H).
// ---------------------------------------------------------------------------
__global__ __launch_bounds__(256) void attn3_kernel(
    const float* __restrict__ q, const float* __restrict__ k,
    const float* __restrict__ v, float* __restrict__ obuf)
{
    extern __shared__ float sm[];
    float* Qs = sm;                  // [128][68]
    float* Ks = Qs + 128 * 68;       // [64][68]  row-major [j][d]
    float* Vs = Ks + 64 * 68;        // [64][68]  row-major [j][d]
    float* Ps = Vs + 64 * 68;        // [128][68]

    int t = threadIdx.x;
    int lane = t & 31, w = t >> 5;
    int g = lane >> 2, tid4 = lane & 3;
    int qb = w * 16;                 // warp's q-row base within the 128-row tile

    int nh = blockIdx.y;
    int n = nh >> 3, hh = nh & 7;
    int q0 = blockIdx.x * 128;
    const float* qp = q + ((long)nh * S_ + q0) * HD_;
    const float* kp = k + (long)nh * S_ * HD_;
    const float* vp = v + (long)nh * S_ * HD_;
    const float inv_scale = 0.044194173824159216f;  // 1/sqrt(512)

    // load Q (128x64) scaled, row-major pad 68
    for (int i = t; i < 2048; i += 256) {      // float4 index
        int r = i >> 4, c4 = (i & 15) * 4;
        float4 f = *(const float4*)(qp + r * HD_ + c4);
        f.x *= inv_scale; f.y *= inv_scale; f.z *= inv_scale; f.w *= inv_scale;
        *(float4*)&Qs[r * 68 + c4] = f;
    }

    float o[8][4] = {};              // O fragments: 8 d-ntiles x 4
    float m0r = -1e30f, m1r = -1e30f, l0 = 0.f, l1 = 0.f;
    __syncthreads();

    for (int kt = 0; kt < 16; kt++) {
        const float* kbt = kp + (long)kt * 64 * HD_;
        const float* vbt = vp + (long)kt * 64 * HD_;
        for (int i = t; i < 1024; i += 256) {  // 64x64 floats each
            int r = i >> 4, c4 = (i & 15) * 4;
            *(float4*)&Ks[r * 68 + c4] = *(const float4*)(kbt + r * HD_ + c4);
            *(float4*)&Vs[r * 68 + c4] = *(const float4*)(vbt + r * HD_ + c4);
        }
        __syncthreads();

        // S = Q K^T  (16 x 64 per warp)
        float s[8][4] = {};
        #pragma unroll
        for (int ch = 0; ch < 8; ch++) {
            int kb = ch * 8;
            unsigned ahi[4], alo[4];
            tf32_split(Qs[(qb + g) * 68 + kb + tid4],         ahi[0], alo[0]);
            tf32_split(Qs[(qb + 8 + g) * 68 + kb + tid4],     ahi[1], alo[1]);
            tf32_split(Qs[(qb + g) * 68 + kb + tid4 + 4],     ahi[2], alo[2]);
            tf32_split(Qs[(qb + 8 + g) * 68 + kb + tid4 + 4], ahi[3], alo[3]);
            #pragma unroll
            for (int nt = 0; nt < 8; nt++) {
                unsigned bhi[2], blo[2];
                tf32_split(Ks[(nt * 8 + g) * 68 + kb + tid4],     bhi[0], blo[0]);
                tf32_split(Ks[(nt * 8 + g) * 68 + kb + tid4 + 4], bhi[1], blo[1]);
                mma_m16n8k8(s[nt], ahi, bhi);
                mma_m16n8k8(s[nt], ahi, blo);
                mma_m16n8k8(s[nt], alo, bhi);
            }
        }

        // online softmax: lane rows r0=qb+g (frags 0,1), r1=qb+8+g (frags 2,3)
        float mt0 = -1e30f, mt1 = -1e30f;
        #pragma unroll
        for (int nt = 0; nt < 8; nt++) {
            mt0 = fmaxf(mt0, fmaxf(s[nt][0], s[nt][1]));
            mt1 = fmaxf(mt1, fmaxf(s[nt][2], s[nt][3]));
        }
        mt0 = fmaxf(mt0, __shfl_xor_sync(0xffffffffu, mt0, 1));
        mt0 = fmaxf(mt0, __shfl_xor_sync(0xffffffffu, mt0, 2));
        mt1 = fmaxf(mt1, __shfl_xor_sync(0xffffffffu, mt1, 1));
        mt1 = fmaxf(mt1, __shfl_xor_sync(0xffffffffu, mt1, 2));
        float mn0 = fmaxf(m0r, mt0), mn1 = fmaxf(m1r, mt1);
        float al0 = __expf(m0r - mn0), al1 = __expf(m1r - mn1);
        m0r = mn0; m1r = mn1;
        float ls0 = 0.f, ls1 = 0.f;
        #pragma unroll
        for (int nt = 0; nt < 8; nt++) {
            s[nt][0] = __expf(s[nt][0] - mn0); ls0 += s[nt][0];
            s[nt][1] = __expf(s[nt][1] - mn0); ls0 += s[nt][1];
            s[nt][2] = __expf(s[nt][2] - mn1); ls1 += s[nt][2];
            s[nt][3] = __expf(s[nt][3] - mn1); ls1 += s[nt][3];
        }
        ls0 += __shfl_xor_sync(0xffffffffu, ls0, 1);
        ls0 += __shfl_xor_sync(0xffffffffu, ls0, 2);
        ls1 += __shfl_xor_sync(0xffffffffu, ls1, 1);
        ls1 += __shfl_xor_sync(0xffffffffu, ls1, 2);
        l0 = l0 * al0 + ls0; l1 = l1 * al1 + ls1;
        #pragma unroll
        for (int nt = 0; nt < 8; nt++) {
            o[nt][0] *= al0; o[nt][1] *= al0;
            o[nt][2] *= al1; o[nt][3] *= al1;
        }

        // P fragments -> smem (warp-private rows; cross-lane read needs syncwarp)
        #pragma unroll
        for (int nt = 0; nt < 8; nt++) {
            *(float2*)&Ps[(qb + g) * 68 + nt * 8 + tid4 * 2] =
                make_float2(s[nt][0], s[nt][1]);
            *(float2*)&Ps[(qb + 8 + g) * 68 + nt * 8 + tid4 * 2] =
                make_float2(s[nt][2], s[nt][3]);
        }
        __syncwarp();

        // O += P V  (k-dim = 64 keys, 8 chunks; n-dim = 64 d, 8 ntiles)
        #pragma unroll
        for (int ch = 0; ch < 8; ch++) {
            int jb = ch * 8;
            unsigned ahi[4], alo[4];
            tf32_split(Ps[(qb + g) * 68 + jb + tid4],         ahi[0], alo[0]);
            tf32_split(Ps[(qb + 8 + g) * 68 + jb + tid4],     ahi[1], alo[1]);
            tf32_split(Ps[(qb + g) * 68 + jb + tid4 + 4],     ahi[2], alo[2]);
            tf32_split(Ps[(qb + 8 + g) * 68 + jb + tid4 + 4], ahi[3], alo[3]);
            #pragma unroll
            for (int nt = 0; nt < 8; nt++) {
                unsigned bhi[2], blo[2];
                tf32_split(Vs[(jb + tid4) * 68 + nt * 8 + g],     bhi[0], blo[0]);
                tf32_split(Vs[(jb + tid4 + 4) * 68 + nt * 8 + g], bhi[1], blo[1]);
                mma_m16n8k8(o[nt], ahi, bhi);
                mma_m16n8k8(o[nt], ahi, blo);
                mma_m16n8k8(o[nt], alo, bhi);
            }
        }
        __syncthreads();   // all warps done with Ks/Vs (and P WAR) before next tile
    }

    // epilogue: normalize and store (rows r0, r1; cols 2*tid4 within each n8)
    float i0 = 1.0f / l0, i1 = 1.0f / l1;
    long r0 = (long)(n * S_ + q0 + qb + g) * E_ + hh * HD_;
    long r1 = (long)(n * S_ + q0 + qb + 8 + g) * E_ + hh * HD_;
    #pragma unroll
    for (int nt = 0; nt < 8; nt++) {
        int col = nt * 8 + tid4 * 2;
        *(float2*)&obuf[r0 + col] = make_float2(o[nt][0] * i0, o[nt][1] * i0);
        *(float2*)&obuf[r1 + col] = make_float2(o[nt][2] * i1, o[nt][3] * i1);
    }
}

// ---------------------------------------------------------------------------
// out = LayerNorm(a + b) * g + be ; one block per row of 512, 128 threads
// ---------------------------------------------------------------------------
__global__ __launch_bounds__(128) void add_ln_kernel(
    const float* __restrict__ a, const float* __restrict__ b,
    const float* __restrict__ g, const float* __restrict__ be,
    float* __restrict__ out)
{
    __shared__ float sha[4], shb[4];
    int row = blockIdx.x, t = threadIdx.x;
    float4 x = ((const float4*)(a + (long)row * E_))[t];
    float4 y = ((const float4*)(b + (long)row * E_))[t];
    x.x += y.x; x.y += y.y; x.z += y.z; x.w += y.w;

    float s  = x.x + x.y + x.z + x.w;
    float s2 = x.x * x.x + x.y * x.y + x.z * x.z + x.w * x.w;
    #pragma unroll
    for (int m = 16; m; m >>= 1) {
        s  += __shfl_xor_sync(0xffffffffu, s,  m);
        s2 += __shfl_xor_sync(0xffffffffu, s2, m);
    }
    int w = t >> 5;
    if ((t & 31) == 0) { sha[w] = s; shb[w] = s2; }
    __syncthreads();
    s  = sha[0] + sha[1] + sha[2] + sha[3];
    s2 = shb[0] + shb[1] + shb[2] + shb[3];

    float mean = s * (1.0f / E_);
    float var  = s2 * (1.0f / E_) - mean * mean;
    float r    = rsqrtf(var + 1e-5f);

    int e = t * 4;
    float4 o;
    o.x = (x.x - mean) * r * g[e + 0] + be[e + 0];
    o.y = (x.y - mean) * r * g[e + 1] + be[e + 1];
    o.z = (x.z - mean) * r * g[e + 2] + be[e + 2];
    o.w = (x.w - mean) * r * g[e + 3] + be[e + 3];
    ((float4*)(out + (long)row * E_))[t] = o;
}

// ---------------------------------------------------------------------------
// Final pointwise conv: out[n][o][s] = sum_e h[n][s][e]*Wfin[e][o] + bfin[o]
// grid (NS/64), block 256; K=512, Nn=64, transposed store
// ---------------------------------------------------------------------------
__global__ __launch_bounds__(256) void final_kernel(
    const float* __restrict__ h, const float* __restrict__ Wfin,
    const float* __restrict__ bfin, float* __restrict__ out)
{
    __shared__ float As[16][64];
    __shared__ float Bs[16][64];
    int t = threadIdx.x, tx = t & 15, ty = t >> 4;
    int m0 = blockIdx.x * 64;

    int lm = t >> 2;
    int lk = (t & 3) * 4;
    int bk = t >> 4;
    int bn = (t & 15) * 4;
    const float* Aptr = h + (long)(m0 + lm) * E_ + lk;
    const float* Bptr = Wfin + (long)bk * O_ + bn;

    float acc[4][4] = {};
    for (int k0 = 0; k0 < E_; k0 += 16) {
        float4 av = *(const float4*)(Aptr + k0);
        As[lk + 0][lm] = av.x; As[lk + 1][lm] = av.y;
        As[lk + 2][lm] = av.z; As[lk + 3][lm] = av.w;
        *(float4*)&Bs[bk][bn] = *(const float4*)(Bptr + (long)k0 * O_);
        __syncthreads();
        #pragma unroll
        for (int kk = 0; kk < 16; kk++) {
            float4 a4 = *(const float4*)&As[kk][ty * 4];
            float4 b4 = *(const float4*)&Bs[kk][tx * 4];
            float a[4] = {a4.x, a4.y, a4.z, a4.w};
            float bb[4] = {b4.x, b4.y, b4.z, b4.w};
            #pragma unroll
            for (int i = 0; i < 4; i++)
                #pragma unroll
                for (int j = 0; j < 4; j++) acc[i][j] += a[i] * bb[j];
        }
        __syncthreads();
    }

    #pragma unroll
    for (int i = 0; i < 4; i++) {
        int m = m0 + ty * 4 + i;
        int n = m >> 10, s = m & 1023;
        #pragma unroll
        for (int j = 0; j < 4; j++) {
            int oo = tx * 4 + j;
            out[((long)(n * O_ + oo)) * S_ + s] = acc[i][j] + bfin[oo];
        }
    }
}

// ---------------------------------------------------------------------------
extern "C" void kernel_launch(void* const* d_in, const int* in_sizes, int n_in,
                              void* d_out, int out_size)
{
    (void)in_sizes; (void)n_in; (void)out_size;
    const float* x       = (const float*)d_in[0];
    const float* W_first = (const float*)d_in[1];
    const float* b_first = (const float*)d_in[2];
    const float* pos     = (const float*)d_in[3];
    const float* Wq      = (const float*)d_in[4];
    const float* bq      = (const float*)d_in[5];
    const float* Wk      = (const float*)d_in[6];
    const float* bk      = (const float*)d_in[7];
    const float* Wv      = (const float*)d_in[8];
    const float* bv      = (const float*)d_in[9];
    const float* Wo      = (const float*)d_in[10];
    const float* bo      = (const float*)d_in[11];
    const float* g1      = (const float*)d_in[12];
    const float* be1     = (const float*)d_in[13];
    const float* Wf1     = (const float*)d_in[14];
    const float* bf1     = (const float*)d_in[15];
    const float* Wf2     = (const float*)d_in[16];
    const float* bf2     = (const float*)d_in[17];
    const float* g2      = (const float*)d_in[18];
    const float* be2     = (const float*)d_in[19];
    const float* Wfin    = (const float*)d_in[20];
    const float* bfin    = (const float*)d_in[21];
    float* out = (float*)d_out;

    float *h, *hx, *tmp, *qb, *kb, *vb, *ob, *ff;
    cudaGetSymbolAddress((void**)&h,   g_h);
    cudaGetSymbolAddress((void**)&hx,  g_hx);
    cudaGetSymbolAddress((void**)&tmp, g_t);
    cudaGetSymbolAddress((void**)&qb,  g_q);
    cudaGetSymbolAddress((void**)&kb,  g_k);
    cudaGetSymbolAddress((void**)&vb,  g_v);
    cudaGetSymbolAddress((void**)&ob,  g_o);
    cudaGetSymbolAddress((void**)&ff,  g_ff);

    // Unconditional + idempotent (no static guards; capture-safe host call).
    const int ATTN_SMEM = (128 * 68 + 64 * 68 + 64 * 68 + 128 * 68) * 4; // 104448
    cudaFuncSetAttribute(attn3_kernel,
                         cudaFuncAttributeMaxDynamicSharedMemorySize, ATTN_SMEM);

    embed_kernel<<<dim3(E_ / 64, S_ / 64, N_), 256>>>(x, W_first, b_first, pos, h);

    for (int l = 0; l < L_; l++) {
        qkv_kernel<<<dim3(NS_ / 64, H_, 3), 256>>>(
            h,
            Wq + (long)l * HD_ * HD_, bq + (long)l * HD_,
            Wk + (long)l * HD_ * HD_, bk + (long)l * HD_,
            Wv + (long)l * HD_ * HD_, bv + (long)l * HD_,
            qb, kb, vb);

        attn3_kernel<<<dim3(S_ / 128, N_ * H_), 256, ATTN_SMEM>>>(qb, kb, vb, ob);

        sgemm_tf32_kernel<<<dim3(E_ / 128, NS_ / 128), 256>>>(
            ob, Wo + (long)l * E_ * E_, bo + (long)l * E_, tmp,
            NS_, E_, E_, 0);

        add_ln_kernel<<<NS_, 128>>>(tmp, h, g1 + (long)l * E_, be1 + (long)l * E_, hx);

        sgemm_tf32_kernel<<<dim3(FF_ / 128, NS_ / 128), 256>>>(
            hx, Wf1 + (long)l * E_ * FF_, bf1 + (long)l * FF_, ff,
            NS_, FF_, E_, 1);

        sgemm_tf32_kernel<<<dim3(E_ / 128, NS_ / 128), 256>>>(
            ff, Wf2 + (long)l * FF_ * E_, bf2 + (long)l * E_, tmp,
            NS_, E_, FF_, 0);

        add_ln_kernel<<<NS_, 128>>>(tmp, hx, g2 + (long)l * E_, be2 + (long)l * E_, h);
    }

    final_kernel<<<NS_ / 64, 256>>>(h, Wfin, bfin, out);
}